// round 2
// baseline (speedup 1.0000x reference)
#include <cuda_runtime.h>
#include <cstdint>

#define HID 32
#define MAX_T 2000000

// Scratch: feature buffers reused across both GCN layers (in-place in k_node2).
__device__ float g_xw [(size_t)MAX_T * HID];   // x @ W  (message payload)
__device__ float g_out[(size_t)MAX_T * HID];   // aggregation target / conv output
__device__ float g_dis[MAX_T];                 // deg^-1/2 (with self loop)
__device__ int   g_deg[MAX_T];

__device__ __forceinline__ void red_add_v4(float* addr, float4 v) {
    asm volatile("red.global.add.v4.f32 [%0], {%1,%2,%3,%4};"
                 :: "l"(addr), "f"(v.x), "f"(v.y), "f"(v.z), "f"(v.w)
                 : "memory");
}

__global__ void k_zero_deg(int T) {
    int i = blockIdx.x * blockDim.x + threadIdx.x;
    if (i < T) g_deg[i] = 0;
}

__global__ void k_degree(const int* __restrict__ ei, int M) {
    int e = blockIdx.x * blockDim.x + threadIdx.x;
    if (e < M) atomicAdd(&g_deg[ei[M + e]], 1);
}

// Triplet message receive + dis + layer-1 xw + layer-1 out init.
__global__ void k_node1(const float* __restrict__ ec,
                        const float* __restrict__ t12, const float* __restrict__ t13,
                        const float* __restrict__ t23,
                        const int* __restrict__ c12, const int* __restrict__ c13,
                        const int* __restrict__ c23,
                        const float* __restrict__ cnt,
                        const float* __restrict__ W1, const float* __restrict__ b1,
                        float* __restrict__ o_t12, float* __restrict__ o_t13,
                        float* __restrict__ o_t23, int T) {
    __shared__ float W1s[96];
    __shared__ float b1s[HID];
    int tx = threadIdx.x;
    if (tx < 96)  W1s[tx] = W1[tx];
    if (tx < HID) b1s[tx] = b1[tx];
    __syncthreads();
    int i = blockIdx.x * blockDim.x + tx;
    if (i >= T) return;

    int i12 = c12[i], i13 = c13[i], i23 = c23[i];
    float a = t12[i] + ec[i12] / cnt[i12];
    float b = t13[i] + ec[i13] / cnt[i13];
    float c = t23[i] + ec[i23] / cnt[i23];
    o_t12[i] = a; o_t13[i] = b; o_t23[i] = c;   // stage t' for the head kernel

    float dis = rsqrtf((float)g_deg[i] + 1.0f);
    g_dis[i] = dis;
    float dis2 = dis * dis;

    float xw[HID];
#pragma unroll
    for (int j = 0; j < HID; j++)
        xw[j] = a * W1s[j] + b * W1s[32 + j] + c * W1s[64 + j];

    float4* px = (float4*)(g_xw  + (size_t)i * HID);
    float4* po = (float4*)(g_out + (size_t)i * HID);
#pragma unroll
    for (int q = 0; q < 8; q++) {
        px[q] = make_float4(xw[4*q], xw[4*q+1], xw[4*q+2], xw[4*q+3]);
        po[q] = make_float4(xw[4*q+0] * dis2 + b1s[4*q+0],
                            xw[4*q+1] * dis2 + b1s[4*q+1],
                            xw[4*q+2] * dis2 + b1s[4*q+2],
                            xw[4*q+3] * dis2 + b1s[4*q+3]);
    }
}

// Edge aggregation: 8 lanes per edge, one float4 of features per lane.
__global__ void k_scatter(const int* __restrict__ ei, int M) {
    int tid = blockIdx.x * blockDim.x + threadIdx.x;
    int e = tid >> 3;
    if (e >= M) return;
    int f = (tid & 7) * 4;
    int src = __ldg(&ei[e]);
    int dst = __ldg(&ei[M + e]);
    float norm = g_dis[src] * g_dis[dst];
    float4 v = *(const float4*)(g_xw + (size_t)src * HID + f);
    v.x *= norm; v.y *= norm; v.z *= norm; v.w *= norm;
    red_add_v4(g_out + (size_t)dst * HID + f, v);
}

// relu(layer-1 out) @ W2, in place: g_xw <- xw2, g_out <- xw2*dis2 + b2.
__global__ void k_node2(const float* __restrict__ W2, const float* __restrict__ b2, int T) {
    __shared__ float4 W2s[HID * 8];   // W2[k][j] as float4 over j
    __shared__ float  b2s[HID];
    int tx = threadIdx.x;
    W2s[tx] = ((const float4*)W2)[tx];     // 256 threads x 16B = 4KB = full W2
    if (tx < HID) b2s[tx] = b2[tx];
    __syncthreads();
    int i = blockIdx.x * blockDim.x + tx;
    if (i >= T) return;

    float4* po = (float4*)(g_out + (size_t)i * HID);
    float4* px = (float4*)(g_xw  + (size_t)i * HID);
    float h[HID];
#pragma unroll
    for (int q = 0; q < 8; q++) {
        float4 v = po[q];
        h[4*q+0] = fmaxf(v.x, 0.f); h[4*q+1] = fmaxf(v.y, 0.f);
        h[4*q+2] = fmaxf(v.z, 0.f); h[4*q+3] = fmaxf(v.w, 0.f);
    }
    float acc[HID];
#pragma unroll
    for (int j = 0; j < HID; j++) acc[j] = 0.f;
#pragma unroll
    for (int k = 0; k < HID; k++) {
        float hk = h[k];
#pragma unroll
        for (int j4 = 0; j4 < 8; j4++) {
            float4 w = W2s[k * 8 + j4];
            acc[4*j4+0] += hk * w.x; acc[4*j4+1] += hk * w.y;
            acc[4*j4+2] += hk * w.z; acc[4*j4+3] += hk * w.w;
        }
    }
    float dis = g_dis[i];
    float dis2 = dis * dis;
#pragma unroll
    for (int q = 0; q < 8; q++) {
        px[q] = make_float4(acc[4*q], acc[4*q+1], acc[4*q+2], acc[4*q+3]);
        po[q] = make_float4(acc[4*q+0] * dis2 + b2s[4*q+0],
                            acc[4*q+1] * dis2 + b2s[4*q+1],
                            acc[4*q+2] * dis2 + b2s[4*q+2],
                            acc[4*q+3] * dis2 + b2s[4*q+3]);
    }
}

// Base edge costs output (zeroed where counter>0), before head-kernel atomics.
__global__ void k_edgebase(const float* __restrict__ ec, const float* __restrict__ cnt,
                           float* __restrict__ o_ec, int E) {
    int e = blockIdx.x * blockDim.x + threadIdx.x;
    if (e < E) o_ec[e] = (cnt[e] > 0.f) ? 0.f : ec[e];
}

// Head: delta = relu(out2) @ Wout + bout; update t outputs; scatter delta to edges.
__global__ void k_final(const float* __restrict__ Wout, const float* __restrict__ bout,
                        const int* __restrict__ c12, const int* __restrict__ c13,
                        const int* __restrict__ c23,
                        float* __restrict__ o_ec,
                        float* __restrict__ o_t12, float* __restrict__ o_t13,
                        float* __restrict__ o_t23, int T) {
    __shared__ float Ws[96];
    __shared__ float bs[3];
    int tx = threadIdx.x;
    if (tx < 96) Ws[tx] = Wout[tx];
    if (tx < 3)  bs[tx] = bout[tx];
    __syncthreads();
    int i = blockIdx.x * blockDim.x + tx;
    if (i >= T) return;

    const float4* po = (const float4*)(g_out + (size_t)i * HID);
    float h[HID];
#pragma unroll
    for (int q = 0; q < 8; q++) {
        float4 v = po[q];
        h[4*q+0] = fmaxf(v.x, 0.f); h[4*q+1] = fmaxf(v.y, 0.f);
        h[4*q+2] = fmaxf(v.z, 0.f); h[4*q+3] = fmaxf(v.w, 0.f);
    }
    float d0 = bs[0], d1 = bs[1], d2 = bs[2];
#pragma unroll
    for (int j = 0; j < HID; j++) {
        float hj = h[j];
        d0 += hj * Ws[j * 3 + 0];
        d1 += hj * Ws[j * 3 + 1];
        d2 += hj * Ws[j * 3 + 2];
    }
    o_t12[i] = o_t12[i] - d0;
    o_t13[i] = o_t13[i] - d1;
    o_t23[i] = o_t23[i] - d2;
    atomicAdd(&o_ec[c12[i]], d0);
    atomicAdd(&o_ec[c13[i]], d1);
    atomicAdd(&o_ec[c23[i]], d2);
}

extern "C" void kernel_launch(void* const* d_in, const int* in_sizes, int n_in,
                              void* d_out, int out_size) {
    const float* ec   = (const float*)d_in[0];
    const float* t12  = (const float*)d_in[1];
    const float* t13  = (const float*)d_in[2];
    const float* t23  = (const float*)d_in[3];
    const int*   c12  = (const int*)  d_in[4];
    const int*   c13  = (const int*)  d_in[5];
    const int*   c23  = (const int*)  d_in[6];
    const float* cnt  = (const float*)d_in[7];
    const int*   ei   = (const int*)  d_in[8];
    const float* W1   = (const float*)d_in[9];
    const float* b1   = (const float*)d_in[10];
    const float* W2   = (const float*)d_in[11];
    const float* b2   = (const float*)d_in[12];
    const float* Wout = (const float*)d_in[13];
    const float* bout = (const float*)d_in[14];

    int E = in_sizes[0];
    int T = in_sizes[1];
    int M = in_sizes[8] / 2;

    float* o     = (float*)d_out;
    float* o_ec  = o;
    float* o_t12 = o + E;
    float* o_t13 = o + E + (size_t)T;
    float* o_t23 = o + E + (size_t)2 * T;

    const int B = 256;
    int gT = (T + B - 1) / B;
    int gM = (M + B - 1) / B;
    int gS = (int)(((size_t)M * 8 + B - 1) / B);
    int gE = (E + B - 1) / B;

    k_zero_deg<<<gT, B>>>(T);
    k_degree<<<gM, B>>>(ei, M);
    k_node1<<<gT, B>>>(ec, t12, t13, t23, c12, c13, c23, cnt, W1, b1,
                       o_t12, o_t13, o_t23, T);
    k_scatter<<<gS, B>>>(ei, M);        // layer 1 aggregation
    k_node2<<<gT, B>>>(W2, b2, T);
    k_scatter<<<gS, B>>>(ei, M);        // layer 2 aggregation
    k_edgebase<<<gE, B>>>(ec, cnt, o_ec, E);
    k_final<<<gT, B>>>(Wout, bout, c12, c13, c23, o_ec, o_t12, o_t13, o_t23, T);
}

// round 3
// speedup vs baseline: 1.2384x; 1.2384x over previous
#include <cuda_runtime.h>
#include <cstdint>

#define HID 32
#define MAX_T 2000000

// Scratch buffers.
__device__ float4 g_tri4[MAX_T];                  // (a,b,c)*dis, premultiplied by src dis
__device__ float4 g_agg3[MAX_T];                  // layer-1 aggregation (3-dim + pad)
__device__ float  g_hs  [(size_t)MAX_T * HID];    // relu(out1) * dis (layer-2 messages)
__device__ float  g_agg [(size_t)MAX_T * HID];    // layer-2 aggregation
__device__ float  g_dis [MAX_T];                  // deg^-1/2 (with self loop)
__device__ int    g_deg [MAX_T];

__device__ __forceinline__ void red_add_v4(float* addr, float4 v) {
    asm volatile("red.global.add.v4.f32 [%0], {%1,%2,%3,%4};"
                 :: "l"(addr), "f"(v.x), "f"(v.y), "f"(v.z), "f"(v.w)
                 : "memory");
}

__global__ void k_zero_deg(int T) {
    int i = blockIdx.x * blockDim.x + threadIdx.x;
    if (i < T) g_deg[i] = 0;
}

__global__ void k_degree(const int* __restrict__ ei, int M) {
    int e = blockIdx.x * blockDim.x + threadIdx.x;
    if (e < M) atomicAdd(&g_deg[ei[M + e]], 1);
}

// Triplet message receive; stage t' in d_out; dis; premultiplied tri; zero agg3.
__global__ void k_node1(const float* __restrict__ ec,
                        const float* __restrict__ t12, const float* __restrict__ t13,
                        const float* __restrict__ t23,
                        const int* __restrict__ c12, const int* __restrict__ c13,
                        const int* __restrict__ c23,
                        const float* __restrict__ cnt,
                        float* __restrict__ o_t12, float* __restrict__ o_t13,
                        float* __restrict__ o_t23, int T) {
    int i = blockIdx.x * blockDim.x + threadIdx.x;
    if (i >= T) return;
    int i12 = c12[i], i13 = c13[i], i23 = c23[i];
    float a = t12[i] + ec[i12] / cnt[i12];
    float b = t13[i] + ec[i13] / cnt[i13];
    float c = t23[i] + ec[i23] / cnt[i23];
    o_t12[i] = a; o_t13[i] = b; o_t23[i] = c;

    float dis = rsqrtf((float)g_deg[i] + 1.0f);
    g_dis[i]  = dis;
    g_tri4[i] = make_float4(a * dis, b * dis, c * dis, 0.f);
    g_agg3[i] = make_float4(0.f, 0.f, 0.f, 0.f);
}

// Layer-1 aggregation over the RAW 3-dim features (both buffers L2-resident).
__global__ void k_scatter3(const int* __restrict__ ei, int M) {
    int e = blockIdx.x * blockDim.x + threadIdx.x;
    if (e >= M) return;
    int src = __ldg(&ei[e]);
    int dst = __ldg(&ei[M + e]);
    float4 v = *(const float4*)&g_tri4[src];
    red_add_v4((float*)&g_agg3[dst], v);
}

// out1 = (dis*(agg3+tri_s))@W1 + b1 ; h = relu(out1) ; store h*dis ; zero agg32.
__global__ void k_node2a(const float* __restrict__ W1, const float* __restrict__ b1, int T) {
    __shared__ float W1s[96];
    __shared__ float b1s[HID];
    int tx = threadIdx.x;
    if (tx < 96)  W1s[tx] = W1[tx];
    if (tx < HID) b1s[tx] = b1[tx];
    __syncthreads();
    int i = blockIdx.x * blockDim.x + tx;
    if (i >= T) return;

    float dis = g_dis[i];
    float4 ag = g_agg3[i];
    float4 ts = g_tri4[i];
    float va = dis * (ag.x + ts.x);
    float vb = dis * (ag.y + ts.y);
    float vc = dis * (ag.z + ts.z);

    float4* ph = (float4*)(g_hs  + (size_t)i * HID);
    float4* pa = (float4*)(g_agg + (size_t)i * HID);
    const float4 z4 = make_float4(0.f, 0.f, 0.f, 0.f);
#pragma unroll
    for (int q = 0; q < 8; q++) {
        float h0 = fmaxf(va * W1s[4*q+0] + vb * W1s[32+4*q+0] + vc * W1s[64+4*q+0] + b1s[4*q+0], 0.f);
        float h1 = fmaxf(va * W1s[4*q+1] + vb * W1s[32+4*q+1] + vc * W1s[64+4*q+1] + b1s[4*q+1], 0.f);
        float h2 = fmaxf(va * W1s[4*q+2] + vb * W1s[32+4*q+2] + vc * W1s[64+4*q+2] + b1s[4*q+2], 0.f);
        float h3 = fmaxf(va * W1s[4*q+3] + vb * W1s[32+4*q+3] + vc * W1s[64+4*q+3] + b1s[4*q+3], 0.f);
        ph[q] = make_float4(h0 * dis, h1 * dis, h2 * dis, h3 * dis);
        pa[q] = z4;
    }
}

// Layer-2 aggregation of premultiplied h: 8 lanes per edge, one float4 each.
__global__ void k_scatter32(const int* __restrict__ ei, int M) {
    int tid = blockIdx.x * blockDim.x + threadIdx.x;
    int e = tid >> 3;
    if (e >= M) return;
    int f = (tid & 7) * 4;
    int src = __ldg(&ei[e]);
    int dst = __ldg(&ei[M + e]);
    float4 v = *(const float4*)(g_hs + (size_t)src * HID + f);
    red_add_v4(g_agg + (size_t)dst * HID + f, v);
}

// Base edge costs output (zeroed where counter>0), before head-kernel atomics.
__global__ void k_edgebase(const float* __restrict__ ec, const float* __restrict__ cnt,
                           float* __restrict__ o_ec, int E) {
    int e = blockIdx.x * blockDim.x + threadIdx.x;
    if (e < E) o_ec[e] = (cnt[e] > 0.f) ? 0.f : ec[e];
}

// Fused: out2 = (dis*(agg+hs))@W2 + b2 ; h2=relu ; delta=h2@Wout+bout ;
// t updates and edge scatter.
__global__ void k_final(const float* __restrict__ W2, const float* __restrict__ b2,
                        const float* __restrict__ Wout, const float* __restrict__ bout,
                        const int* __restrict__ c12, const int* __restrict__ c13,
                        const int* __restrict__ c23,
                        float* __restrict__ o_ec,
                        float* __restrict__ o_t12, float* __restrict__ o_t13,
                        float* __restrict__ o_t23, int T) {
    __shared__ float4 W2s[HID * 8];   // W2[k][j] as float4 over j
    __shared__ float  b2s[HID];
    __shared__ float  Wos[96];
    __shared__ float  bos[3];
    int tx = threadIdx.x;
    W2s[tx] = ((const float4*)W2)[tx];     // 256 threads x 16B = full 32x32 W2
    if (tx < HID) b2s[tx] = b2[tx];
    if (tx < 96)  Wos[tx] = Wout[tx];
    if (tx < 3)   bos[tx] = bout[tx];
    __syncthreads();
    int i = blockIdx.x * blockDim.x + tx;
    if (i >= T) return;

    float dis = g_dis[i];
    const float4* pa = (const float4*)(g_agg + (size_t)i * HID);
    const float4* ph = (const float4*)(g_hs  + (size_t)i * HID);

    float v[HID];
#pragma unroll
    for (int q = 0; q < 8; q++) {
        float4 a = pa[q];
        float4 h = ph[q];
        v[4*q+0] = dis * (a.x + h.x);
        v[4*q+1] = dis * (a.y + h.y);
        v[4*q+2] = dis * (a.z + h.z);
        v[4*q+3] = dis * (a.w + h.w);
    }
    float acc[HID];
#pragma unroll
    for (int j = 0; j < HID; j++) acc[j] = b2s[j];
#pragma unroll
    for (int k = 0; k < HID; k++) {
        float vk = v[k];
#pragma unroll
        for (int j4 = 0; j4 < 8; j4++) {
            float4 w = W2s[k * 8 + j4];
            acc[4*j4+0] += vk * w.x; acc[4*j4+1] += vk * w.y;
            acc[4*j4+2] += vk * w.z; acc[4*j4+3] += vk * w.w;
        }
    }
    float d0 = bos[0], d1 = bos[1], d2 = bos[2];
#pragma unroll
    for (int j = 0; j < HID; j++) {
        float hj = fmaxf(acc[j], 0.f);
        d0 += hj * Wos[j * 3 + 0];
        d1 += hj * Wos[j * 3 + 1];
        d2 += hj * Wos[j * 3 + 2];
    }
    o_t12[i] = o_t12[i] - d0;
    o_t13[i] = o_t13[i] - d1;
    o_t23[i] = o_t23[i] - d2;
    atomicAdd(&o_ec[c12[i]], d0);
    atomicAdd(&o_ec[c13[i]], d1);
    atomicAdd(&o_ec[c23[i]], d2);
}

extern "C" void kernel_launch(void* const* d_in, const int* in_sizes, int n_in,
                              void* d_out, int out_size) {
    const float* ec   = (const float*)d_in[0];
    const float* t12  = (const float*)d_in[1];
    const float* t13  = (const float*)d_in[2];
    const float* t23  = (const float*)d_in[3];
    const int*   c12  = (const int*)  d_in[4];
    const int*   c13  = (const int*)  d_in[5];
    const int*   c23  = (const int*)  d_in[6];
    const float* cnt  = (const float*)d_in[7];
    const int*   ei   = (const int*)  d_in[8];
    const float* W1   = (const float*)d_in[9];
    const float* b1   = (const float*)d_in[10];
    const float* W2   = (const float*)d_in[11];
    const float* b2   = (const float*)d_in[12];
    const float* Wout = (const float*)d_in[13];
    const float* bout = (const float*)d_in[14];

    int E = in_sizes[0];
    int T = in_sizes[1];
    int M = in_sizes[8] / 2;

    float* o     = (float*)d_out;
    float* o_ec  = o;
    float* o_t12 = o + E;
    float* o_t13 = o + E + (size_t)T;
    float* o_t23 = o + E + (size_t)2 * T;

    const int B = 256;
    int gT = (T + B - 1) / B;
    int gM = (M + B - 1) / B;
    int gS = (int)(((size_t)M * 8 + B - 1) / B);
    int gE = (E + B - 1) / B;

    k_zero_deg<<<gT, B>>>(T);
    k_degree<<<gM, B>>>(ei, M);
    k_node1<<<gT, B>>>(ec, t12, t13, t23, c12, c13, c23, cnt,
                       o_t12, o_t13, o_t23, T);
    k_scatter3<<<gM, B>>>(ei, M);          // layer-1 agg on 3-dim raw features
    k_node2a<<<gT, B>>>(W1, b1, T);
    k_scatter32<<<gS, B>>>(ei, M);         // layer-2 agg on 32-dim h*dis
    k_edgebase<<<gE, B>>>(ec, cnt, o_ec, E);
    k_final<<<gT, B>>>(W2, b2, Wout, bout, c12, c13, c23,
                       o_ec, o_t12, o_t13, o_t23, T);
}

// round 4
// speedup vs baseline: 1.5633x; 1.2623x over previous
#include <cuda_runtime.h>
#include <cstdint>

#define HID 32
#define MAX_T 2000000
#define MAX_M 4000000
#define SCAN_E 2048          // elems per scan block (256 thr * 8)
#define MAX_NB 4096

// Scratch buffers.
__device__ float4 g_tri4[MAX_T];                 // (a,b,c)*dis_src, pad
__device__ float  g_hs  [(size_t)MAX_T * HID];   // relu(out1)*dis (layer-2 messages)
__device__ float  g_dis [MAX_T];                 // deg^-1/2 (with self loop)
__device__ int    g_deg [MAX_T];
__device__ int    g_off [MAX_T];                 // CSR row offsets (exclusive)
__device__ int    g_cursor[MAX_T];
__device__ int    g_csr [MAX_M];                 // src lists grouped by dst
__device__ int    g_bsum[MAX_NB];

__global__ void k_zero_deg(int T) {
    int i = blockIdx.x * blockDim.x + threadIdx.x;
    if (i < T) g_deg[i] = 0;
}

__global__ void k_degree(const int* __restrict__ ei, int M) {
    int e = blockIdx.x * blockDim.x + threadIdx.x;
    if (e < M) atomicAdd(&g_deg[__ldg(&ei[M + e])], 1);
}

// Triplet message receive; stage t' in d_out; dis; premultiplied tri.
__global__ void k_node1(const float* __restrict__ ec,
                        const float* __restrict__ t12, const float* __restrict__ t13,
                        const float* __restrict__ t23,
                        const int* __restrict__ c12, const int* __restrict__ c13,
                        const int* __restrict__ c23,
                        const float* __restrict__ cnt,
                        float* __restrict__ o_t12, float* __restrict__ o_t13,
                        float* __restrict__ o_t23, int T) {
    int i = blockIdx.x * blockDim.x + threadIdx.x;
    if (i >= T) return;
    int i12 = c12[i], i13 = c13[i], i23 = c23[i];
    float a = t12[i] + ec[i12] / cnt[i12];
    float b = t13[i] + ec[i13] / cnt[i13];
    float c = t23[i] + ec[i23] / cnt[i23];
    o_t12[i] = a; o_t13[i] = b; o_t23[i] = c;
    float dis = rsqrtf((float)g_deg[i] + 1.0f);
    g_dis[i]  = dis;
    g_tri4[i] = make_float4(a * dis, b * dis, c * dis, 0.f);
}

// ---- exclusive scan of g_deg -> g_off (3 kernels) ----
__global__ void k_scanA(int T) {
    __shared__ int sh[256];
    int b = blockIdx.x, tx = threadIdx.x;
    int base = b * SCAN_E + tx * 8;
    int s = 0;
#pragma unroll
    for (int k = 0; k < 8; k++) { int i = base + k; if (i < T) s += g_deg[i]; }
    sh[tx] = s; __syncthreads();
    for (int o = 128; o > 0; o >>= 1) { if (tx < o) sh[tx] += sh[tx + o]; __syncthreads(); }
    if (tx == 0) g_bsum[b] = sh[0];
}

__global__ void k_scanB(int nb) {
    __shared__ int sh[1024];
    int tx = threadIdx.x;
    int c = (nb + 1023) >> 10;
    int s = 0;
    for (int k = 0; k < c; k++) { int i = tx * c + k; if (i < nb) s += g_bsum[i]; }
    sh[tx] = s; __syncthreads();
    for (int o = 1; o < 1024; o <<= 1) {
        int v = (tx >= o) ? sh[tx - o] : 0; __syncthreads();
        sh[tx] += v; __syncthreads();
    }
    int excl = (tx == 0) ? 0 : sh[tx - 1];
    for (int k = 0; k < c; k++) {
        int i = tx * c + k;
        if (i < nb) { int v = g_bsum[i]; g_bsum[i] = excl; excl += v; }
    }
}

__global__ void k_scanC(int T) {
    __shared__ int sh[256];
    int b = blockIdx.x, tx = threadIdx.x;
    int base = b * SCAN_E + tx * 8;
    int loc[8]; int s = 0;
#pragma unroll
    for (int k = 0; k < 8; k++) {
        int i = base + k;
        int d = (i < T) ? g_deg[i] : 0;
        loc[k] = s; s += d;
    }
    sh[tx] = s; __syncthreads();
    for (int o = 1; o < 256; o <<= 1) {
        int v = (tx >= o) ? sh[tx - o] : 0; __syncthreads();
        sh[tx] += v; __syncthreads();
    }
    int toff = ((tx == 0) ? 0 : sh[tx - 1]) + g_bsum[b];
#pragma unroll
    for (int k = 0; k < 8; k++) {
        int i = base + k;
        if (i < T) { int o = toff + loc[k]; g_off[i] = o; g_cursor[i] = o; }
    }
}

// Fill CSR: src lists grouped by dst.
__global__ void k_csr(const int* __restrict__ ei, int M) {
    int e = blockIdx.x * blockDim.x + threadIdx.x;
    if (e >= M) return;
    int src = __ldg(&ei[e]);
    int dst = __ldg(&ei[M + e]);
    int pos = atomicAdd(&g_cursor[dst], 1);
    g_csr[pos] = src;
}

// Layer 1 (fully fused): gather+sum raw 3-dim messages, @W1+b1, relu, store h*dis.
__global__ void k_layer1(const float* __restrict__ W1, const float* __restrict__ b1, int T) {
    __shared__ float W1s[96];
    __shared__ float b1s[HID];
    int tx = threadIdx.x;
    if (tx < 96)  W1s[tx] = W1[tx];
    if (tx < HID) b1s[tx] = b1[tx];
    __syncthreads();
    int i = blockIdx.x * blockDim.x + tx;
    if (i >= T) return;

    float dis = g_dis[i];
    float4 sum = g_tri4[i];                 // self loop (already *dis_i)
    int s = g_off[i], d = g_deg[i];
    for (int n = 0; n < d; n++) {
        int src = g_csr[s + n];
        float4 t = g_tri4[src];
        sum.x += t.x; sum.y += t.y; sum.z += t.z;
    }
    float va = dis * sum.x, vb = dis * sum.y, vc = dis * sum.z;

    float4* ph = (float4*)(g_hs + (size_t)i * HID);
#pragma unroll
    for (int q = 0; q < 8; q++) {
        float h0 = fmaxf(va * W1s[4*q+0] + vb * W1s[32+4*q+0] + vc * W1s[64+4*q+0] + b1s[4*q+0], 0.f);
        float h1 = fmaxf(va * W1s[4*q+1] + vb * W1s[32+4*q+1] + vc * W1s[64+4*q+1] + b1s[4*q+1], 0.f);
        float h2 = fmaxf(va * W1s[4*q+2] + vb * W1s[32+4*q+2] + vc * W1s[64+4*q+2] + b1s[4*q+2], 0.f);
        float h3 = fmaxf(va * W1s[4*q+3] + vb * W1s[32+4*q+3] + vc * W1s[64+4*q+3] + b1s[4*q+3], 0.f);
        ph[q] = make_float4(h0 * dis, h1 * dis, h2 * dis, h3 * dis);
    }
}

// Base edge costs output (zeroed where counter>0), before head-kernel atomics.
__global__ void k_edgebase(const float* __restrict__ ec, const float* __restrict__ cnt,
                           float* __restrict__ o_ec, int E) {
    int e = blockIdx.x * blockDim.x + threadIdx.x;
    if (e < E) o_ec[e] = (cnt[e] > 0.f) ? 0.f : ec[e];
}

// Layer 2 + head (fully fused), 8 lanes per dst node.
// gather+sum hs rows, v=dis*sum, acc=v@W2+b2 (shfl-broadcast), relu,
// delta=h2@Wout+bout (8-lane reduce), t updates + edge atomics.
__global__ void k_layer2_final(const float* __restrict__ W2, const float* __restrict__ b2,
                               const float* __restrict__ Wout, const float* __restrict__ bout,
                               const int* __restrict__ c12, const int* __restrict__ c13,
                               const int* __restrict__ c23,
                               float* __restrict__ o_ec,
                               float* __restrict__ o_t12, float* __restrict__ o_t13,
                               float* __restrict__ o_t23, int T) {
    __shared__ float4 W2s[HID * 8];
    __shared__ float  b2s[HID];
    __shared__ float  Wos[96];
    __shared__ float  bos[3];
    int tx = threadIdx.x;
    W2s[tx] = ((const float4*)W2)[tx];
    if (tx < HID) b2s[tx] = b2[tx];
    if (tx < 96)  Wos[tx] = Wout[tx];
    if (tx < 3)   bos[tx] = bout[tx];
    __syncthreads();

    int tid = blockIdx.x * blockDim.x + tx;
    int i  = tid >> 3;
    if (i >= T) return;
    int l8 = tx & 7;

    const float4* hs4 = (const float4*)g_hs;
    float dis = g_dis[i];
    int s = g_off[i], d = g_deg[i];
    float4 sum = hs4[(size_t)i * 8 + l8];          // self loop (already *dis_i)
    for (int n = 0; n < d; n++) {
        int src = g_csr[s + n];
        float4 t = hs4[(size_t)src * 8 + l8];
        sum.x += t.x; sum.y += t.y; sum.z += t.z; sum.w += t.w;
    }
    float4 v = make_float4(dis * sum.x, dis * sum.y, dis * sum.z, dis * sum.w);

    float4 acc = make_float4(b2s[4*l8+0], b2s[4*l8+1], b2s[4*l8+2], b2s[4*l8+3]);
#pragma unroll
    for (int k = 0; k < HID; k++) {
        float comp = ((k & 3) == 0) ? v.x : ((k & 3) == 1) ? v.y : ((k & 3) == 2) ? v.z : v.w;
        float vk = __shfl_sync(0xffffffffu, comp, k >> 2, 8);
        float4 w = W2s[k * 8 + l8];
        acc.x += vk * w.x; acc.y += vk * w.y; acc.z += vk * w.z; acc.w += vk * w.w;
    }
    float h0 = fmaxf(acc.x, 0.f), h1 = fmaxf(acc.y, 0.f);
    float h2 = fmaxf(acc.z, 0.f), h3 = fmaxf(acc.w, 0.f);

    int j = 4 * l8;
    float d0 = h0*Wos[(j+0)*3+0] + h1*Wos[(j+1)*3+0] + h2*Wos[(j+2)*3+0] + h3*Wos[(j+3)*3+0];
    float d1 = h0*Wos[(j+0)*3+1] + h1*Wos[(j+1)*3+1] + h2*Wos[(j+2)*3+1] + h3*Wos[(j+3)*3+1];
    float d2 = h0*Wos[(j+0)*3+2] + h1*Wos[(j+1)*3+2] + h2*Wos[(j+2)*3+2] + h3*Wos[(j+3)*3+2];
#pragma unroll
    for (int o = 1; o < 8; o <<= 1) {
        d0 += __shfl_xor_sync(0xffffffffu, d0, o, 8);
        d1 += __shfl_xor_sync(0xffffffffu, d1, o, 8);
        d2 += __shfl_xor_sync(0xffffffffu, d2, o, 8);
    }
    if (l8 == 0) {
        d0 += bos[0]; d1 += bos[1]; d2 += bos[2];
        o_t12[i] = o_t12[i] - d0;
        o_t13[i] = o_t13[i] - d1;
        o_t23[i] = o_t23[i] - d2;
        atomicAdd(&o_ec[c12[i]], d0);
        atomicAdd(&o_ec[c13[i]], d1);
        atomicAdd(&o_ec[c23[i]], d2);
    }
}

extern "C" void kernel_launch(void* const* d_in, const int* in_sizes, int n_in,
                              void* d_out, int out_size) {
    const float* ec   = (const float*)d_in[0];
    const float* t12  = (const float*)d_in[1];
    const float* t13  = (const float*)d_in[2];
    const float* t23  = (const float*)d_in[3];
    const int*   c12  = (const int*)  d_in[4];
    const int*   c13  = (const int*)  d_in[5];
    const int*   c23  = (const int*)  d_in[6];
    const float* cnt  = (const float*)d_in[7];
    const int*   ei   = (const int*)  d_in[8];
    const float* W1   = (const float*)d_in[9];
    const float* b1   = (const float*)d_in[10];
    const float* W2   = (const float*)d_in[11];
    const float* b2   = (const float*)d_in[12];
    const float* Wout = (const float*)d_in[13];
    const float* bout = (const float*)d_in[14];

    int E = in_sizes[0];
    int T = in_sizes[1];
    int M = in_sizes[8] / 2;

    float* o     = (float*)d_out;
    float* o_ec  = o;
    float* o_t12 = o + E;
    float* o_t13 = o + E + (size_t)T;
    float* o_t23 = o + E + (size_t)2 * T;

    const int B = 256;
    int gT  = (T + B - 1) / B;
    int gM  = (M + B - 1) / B;
    int gE  = (E + B - 1) / B;
    int nb  = (T + SCAN_E - 1) / SCAN_E;       // scan blocks
    int gL2 = (int)(((size_t)T * 8 + B - 1) / B);

    k_zero_deg<<<gT, B>>>(T);
    k_degree<<<gM, B>>>(ei, M);
    k_node1<<<gT, B>>>(ec, t12, t13, t23, c12, c13, c23, cnt,
                       o_t12, o_t13, o_t23, T);
    k_scanA<<<nb, B>>>(T);
    k_scanB<<<1, 1024>>>(nb);
    k_scanC<<<nb, B>>>(T);
    k_csr<<<gM, B>>>(ei, M);
    k_layer1<<<gT, B>>>(W1, b1, T);
    k_edgebase<<<gE, B>>>(ec, cnt, o_ec, E);
    k_layer2_final<<<gL2, B>>>(W2, b2, Wout, bout, c12, c13, c23,
                               o_ec, o_t12, o_t13, o_t23, T);
}

// round 6
// speedup vs baseline: 1.8366x; 1.1749x over previous
#include <cuda_runtime.h>
#include <cuda_fp16.h>
#include <cstdint>

#define HID 32
#define MAX_T 2000000
#define MAX_M 4000000
#define SCAN_E 2048          // elems per scan block (256 thr * 8)
#define MAX_NB 4096

// Scratch buffers.
__device__ float4 g_tri4[MAX_T];                 // (a,b,c)*dis_src, pad
__device__ uint4  g_hs4[(size_t)MAX_T * 4];      // relu(out1)*dis as fp16: 32 halves = 4 uint4 / node
__device__ float  g_dis [MAX_T];                 // deg^-1/2 (with self loop)
__device__ int    g_deg [MAX_T];
__device__ int    g_off [MAX_T];                 // CSR row offsets (exclusive)
__device__ int    g_cursor[MAX_T];
__device__ int    g_csr [MAX_M];                 // src lists grouped by dst
__device__ int    g_bsum[MAX_NB];

__device__ __forceinline__ unsigned h2_to_u32(__half2 h) {
    return *reinterpret_cast<unsigned*>(&h);
}
__device__ __forceinline__ __half2 u32_to_h2(unsigned u) {
    return *reinterpret_cast<__half2*>(&u);
}

__global__ void k_zero_deg(int T) {
    int i = blockIdx.x * blockDim.x + threadIdx.x;
    if (i < T) g_deg[i] = 0;
}

__global__ void k_degree(const int* __restrict__ ei, int M) {
    int e = blockIdx.x * blockDim.x + threadIdx.x;
    if (e < M) atomicAdd(&g_deg[__ldg(&ei[M + e])], 1);
}

// Triplet message receive; stage t' in d_out; dis; premultiplied tri; edge base.
__global__ void k_node1(const float* __restrict__ ec,
                        const float* __restrict__ t12, const float* __restrict__ t13,
                        const float* __restrict__ t23,
                        const int* __restrict__ c12, const int* __restrict__ c13,
                        const int* __restrict__ c23,
                        const float* __restrict__ cnt,
                        float* __restrict__ o_ec,
                        float* __restrict__ o_t12, float* __restrict__ o_t13,
                        float* __restrict__ o_t23, int T, int E) {
    int i = blockIdx.x * blockDim.x + threadIdx.x;
    if (i >= T) return;
    if (i < E) o_ec[i] = (cnt[i] > 0.f) ? 0.f : ec[i];   // fused edge-base pass
    int i12 = c12[i], i13 = c13[i], i23 = c23[i];
    float a = t12[i] + ec[i12] / cnt[i12];
    float b = t13[i] + ec[i13] / cnt[i13];
    float c = t23[i] + ec[i23] / cnt[i23];
    o_t12[i] = a; o_t13[i] = b; o_t23[i] = c;
    float dis = rsqrtf((float)g_deg[i] + 1.0f);
    g_dis[i]  = dis;
    g_tri4[i] = make_float4(a * dis, b * dis, c * dis, 0.f);
}

// ---- exclusive scan of g_deg -> g_off (3 kernels) ----
__global__ void k_scanA(int T) {
    __shared__ int sh[256];
    int b = blockIdx.x, tx = threadIdx.x;
    int base = b * SCAN_E + tx * 8;
    int s = 0;
#pragma unroll
    for (int k = 0; k < 8; k++) { int i = base + k; if (i < T) s += g_deg[i]; }
    sh[tx] = s; __syncthreads();
    for (int o = 128; o > 0; o >>= 1) { if (tx < o) sh[tx] += sh[tx + o]; __syncthreads(); }
    if (tx == 0) g_bsum[b] = sh[0];
}

__global__ void k_scanB(int nb) {
    __shared__ int sh[1024];
    int tx = threadIdx.x;
    int c = (nb + 1023) >> 10;
    int s = 0;
    for (int k = 0; k < c; k++) { int i = tx * c + k; if (i < nb) s += g_bsum[i]; }
    sh[tx] = s; __syncthreads();
    for (int o = 1; o < 1024; o <<= 1) {
        int v = (tx >= o) ? sh[tx - o] : 0; __syncthreads();
        sh[tx] += v; __syncthreads();
    }
    int excl = (tx == 0) ? 0 : sh[tx - 1];
    for (int k = 0; k < c; k++) {
        int i = tx * c + k;
        if (i < nb) { int v = g_bsum[i]; g_bsum[i] = excl; excl += v; }
    }
}

__global__ void k_scanC(int T) {
    __shared__ int sh[256];
    int b = blockIdx.x, tx = threadIdx.x;
    int base = b * SCAN_E + tx * 8;
    int loc[8]; int s = 0;
#pragma unroll
    for (int k = 0; k < 8; k++) {
        int i = base + k;
        int d = (i < T) ? g_deg[i] : 0;
        loc[k] = s; s += d;
    }
    sh[tx] = s; __syncthreads();
    for (int o = 1; o < 256; o <<= 1) {
        int v = (tx >= o) ? sh[tx - o] : 0; __syncthreads();
        sh[tx] += v; __syncthreads();
    }
    int toff = ((tx == 0) ? 0 : sh[tx - 1]) + g_bsum[b];
#pragma unroll
    for (int k = 0; k < 8; k++) {
        int i = base + k;
        if (i < T) { int o = toff + loc[k]; g_off[i] = o; g_cursor[i] = o; }
    }
}

// Fill CSR: src lists grouped by dst.
__global__ void k_csr(const int* __restrict__ ei, int M) {
    int e = blockIdx.x * blockDim.x + threadIdx.x;
    if (e >= M) return;
    int src = __ldg(&ei[e]);
    int dst = __ldg(&ei[M + e]);
    int pos = atomicAdd(&g_cursor[dst], 1);
    g_csr[pos] = src;
}

// Layer 1 (fused): gather+sum raw 3-dim messages, @W1+b1, relu, store h*dis as fp16.
__global__ void k_layer1(const float* __restrict__ W1, const float* __restrict__ b1, int T) {
    __shared__ float W1s[96];
    __shared__ float b1s[HID];
    int tx = threadIdx.x;
    if (tx < 96)  W1s[tx] = W1[tx];
    if (tx < HID) b1s[tx] = b1[tx];
    __syncthreads();
    int i = blockIdx.x * blockDim.x + tx;
    if (i >= T) return;

    float dis = g_dis[i];
    float4 sum = g_tri4[i];                 // self loop (already *dis_i)
    int s = g_off[i], d = g_deg[i];
    for (int n = 0; n < d; n++) {
        int src = g_csr[s + n];
        float4 t = g_tri4[src];
        sum.x += t.x; sum.y += t.y; sum.z += t.z;
    }
    float va = dis * sum.x, vb = dis * sum.y, vc = dis * sum.z;

    float h[HID];
#pragma unroll
    for (int j = 0; j < HID; j++)
        h[j] = fmaxf(va * W1s[j] + vb * W1s[32 + j] + vc * W1s[64 + j] + b1s[j], 0.f) * dis;

    uint4* ph = g_hs4 + (size_t)i * 4;
#pragma unroll
    for (int q = 0; q < 4; q++) {           // each uint4 packs 8 halves
        uint4 u;
        u.x = h2_to_u32(__floats2half2_rn(h[8*q+0], h[8*q+1]));
        u.y = h2_to_u32(__floats2half2_rn(h[8*q+2], h[8*q+3]));
        u.z = h2_to_u32(__floats2half2_rn(h[8*q+4], h[8*q+5]));
        u.w = h2_to_u32(__floats2half2_rn(h[8*q+6], h[8*q+7]));
        ph[q] = u;
    }
}

// Layer 2 + head (fused), 4 lanes per dst node; fp16 message gather, fp32 accum.
__global__ void k_layer2_final(const float* __restrict__ W2, const float* __restrict__ b2,
                               const float* __restrict__ Wout, const float* __restrict__ bout,
                               const int* __restrict__ c12, const int* __restrict__ c13,
                               const int* __restrict__ c23,
                               float* __restrict__ o_ec,
                               float* __restrict__ o_t12, float* __restrict__ o_t13,
                               float* __restrict__ o_t23, int T) {
    __shared__ float4 W2s[HID * 8];   // W2[k][j] as float4 over j
    __shared__ float  b2s[HID];
    __shared__ float  Wos[96];
    __shared__ float  bos[3];
    int tx = threadIdx.x;
    W2s[tx] = ((const float4*)W2)[tx];
    if (tx < HID) b2s[tx] = b2[tx];
    if (tx < 96)  Wos[tx] = Wout[tx];
    if (tx < 3)   bos[tx] = bout[tx];
    __syncthreads();

    int tid = blockIdx.x * blockDim.x + tx;
    int i  = tid >> 2;
    if (i >= T) return;
    int l4 = tx & 3;                  // lane owns h components [8*l4, 8*l4+8)

    float dis = g_dis[i];
    int s = g_off[i], d = g_deg[i];

    float sum[8];
    {
        uint4 u = g_hs4[(size_t)i * 4 + l4];      // self loop (already *dis_i)
        float2 f0 = __half22float2(u32_to_h2(u.x));
        float2 f1 = __half22float2(u32_to_h2(u.y));
        float2 f2 = __half22float2(u32_to_h2(u.z));
        float2 f3 = __half22float2(u32_to_h2(u.w));
        sum[0]=f0.x; sum[1]=f0.y; sum[2]=f1.x; sum[3]=f1.y;
        sum[4]=f2.x; sum[5]=f2.y; sum[6]=f3.x; sum[7]=f3.y;
    }
    for (int n = 0; n < d; n++) {
        int src = g_csr[s + n];
        uint4 u = g_hs4[(size_t)src * 4 + l4];
        float2 f0 = __half22float2(u32_to_h2(u.x));
        float2 f1 = __half22float2(u32_to_h2(u.y));
        float2 f2 = __half22float2(u32_to_h2(u.z));
        float2 f3 = __half22float2(u32_to_h2(u.w));
        sum[0]+=f0.x; sum[1]+=f0.y; sum[2]+=f1.x; sum[3]+=f1.y;
        sum[4]+=f2.x; sum[5]+=f2.y; sum[6]+=f3.x; sum[7]+=f3.y;
    }
    float vr[8];
#pragma unroll
    for (int r = 0; r < 8; r++) vr[r] = dis * sum[r];

    float acc[8];
#pragma unroll
    for (int r = 0; r < 8; r++) acc[r] = b2s[8 * l4 + r];
#pragma unroll
    for (int k = 0; k < HID; k++) {
        float vk = __shfl_sync(0xffffffffu, vr[k & 7], k >> 3, 4);
        float4 wa = W2s[k * 8 + 2 * l4];
        float4 wb = W2s[k * 8 + 2 * l4 + 1];
        acc[0] += vk * wa.x; acc[1] += vk * wa.y; acc[2] += vk * wa.z; acc[3] += vk * wa.w;
        acc[4] += vk * wb.x; acc[5] += vk * wb.y; acc[6] += vk * wb.z; acc[7] += vk * wb.w;
    }

    float d0 = 0.f, d1 = 0.f, d2 = 0.f;
#pragma unroll
    for (int r = 0; r < 8; r++) {
        float hj = fmaxf(acc[r], 0.f);
        int j = 8 * l4 + r;
        d0 += hj * Wos[j * 3 + 0];
        d1 += hj * Wos[j * 3 + 1];
        d2 += hj * Wos[j * 3 + 2];
    }
#pragma unroll
    for (int o = 1; o < 4; o <<= 1) {
        d0 += __shfl_xor_sync(0xffffffffu, d0, o, 4);
        d1 += __shfl_xor_sync(0xffffffffu, d1, o, 4);
        d2 += __shfl_xor_sync(0xffffffffu, d2, o, 4);
    }
    if (l4 == 0) {
        d0 += bos[0]; d1 += bos[1]; d2 += bos[2];
        o_t12[i] = o_t12[i] - d0;
        o_t13[i] = o_t13[i] - d1;
        o_t23[i] = o_t23[i] - d2;
        atomicAdd(&o_ec[c12[i]], d0);
        atomicAdd(&o_ec[c13[i]], d1);
        atomicAdd(&o_ec[c23[i]], d2);
    }
}

extern "C" void kernel_launch(void* const* d_in, const int* in_sizes, int n_in,
                              void* d_out, int out_size) {
    const float* ec   = (const float*)d_in[0];
    const float* t12  = (const float*)d_in[1];
    const float* t13  = (const float*)d_in[2];
    const float* t23  = (const float*)d_in[3];
    const int*   c12  = (const int*)  d_in[4];
    const int*   c13  = (const int*)  d_in[5];
    const int*   c23  = (const int*)  d_in[6];
    const float* cnt  = (const float*)d_in[7];
    const int*   ei   = (const int*)  d_in[8];
    const float* W1   = (const float*)d_in[9];
    const float* b1   = (const float*)d_in[10];
    const float* W2   = (const float*)d_in[11];
    const float* b2   = (const float*)d_in[12];
    const float* Wout = (const float*)d_in[13];
    const float* bout = (const float*)d_in[14];

    int E = in_sizes[0];
    int T = in_sizes[1];
    int M = in_sizes[8] / 2;

    float* o     = (float*)d_out;
    float* o_ec  = o;
    float* o_t12 = o + E;
    float* o_t13 = o + E + (size_t)T;
    float* o_t23 = o + E + (size_t)2 * T;

    const int B = 256;
    int gT  = (T + B - 1) / B;
    int gM  = (M + B - 1) / B;
    int nb  = (T + SCAN_E - 1) / SCAN_E;       // scan blocks
    int gL2 = (int)(((size_t)T * 4 + B - 1) / B);

    k_zero_deg<<<gT, B>>>(T);
    k_degree<<<gM, B>>>(ei, M);
    k_node1<<<gT, B>>>(ec, t12, t13, t23, c12, c13, c23, cnt,
                       o_ec, o_t12, o_t13, o_t23, T, E);
    k_scanA<<<nb, B>>>(T);
    k_scanB<<<1, 1024>>>(nb);
    k_scanC<<<nb, B>>>(T);
    k_csr<<<gM, B>>>(ei, M);
    k_layer1<<<gT, B>>>(W1, b1, T);
    k_layer2_final<<<gL2, B>>>(W2, b2, Wout, bout, c12, c13, c23,
                               o_ec, o_t12, o_t13, o_t23, T);
}

// round 8
// speedup vs baseline: 1.8803x; 1.0238x over previous
#include <cuda_runtime.h>
#include <cuda_fp16.h>
#include <cstdint>

#define HID 32
#define MAX_T 2000000
#define MAX_M 4000000
#define SCAN_E 2048          // elems per scan block (256 thr * 8)
#define MAX_NB 4096

// Scratch buffers.
__device__ float4 g_tri4[MAX_T];                 // (a,b,c)*dis_src, pad
__device__ uint4  g_hs4[(size_t)MAX_T * 4];      // relu(out1)*dis as fp16: 32 halves / node
__device__ int    g_deg [MAX_T];
__device__ int    g_off [MAX_T + 1];             // CSR row offsets (exclusive) + sentinel
__device__ int    g_cursor[MAX_T];
__device__ int    g_csr [MAX_M];                 // src lists grouped by dst
__device__ int    g_bsum[MAX_NB];

__device__ __forceinline__ unsigned h2_to_u32(__half2 h) {
    return *reinterpret_cast<unsigned*>(&h);
}
__device__ __forceinline__ __half2 u32_to_h2(unsigned u) {
    return *reinterpret_cast<__half2*>(&u);
}

__global__ void k_zero_deg(int T) {
    int i = blockIdx.x * blockDim.x + threadIdx.x;
    if (i < T) g_deg[i] = 0;
}

__global__ void k_degree(const int* __restrict__ ei, int M) {
    int e = blockIdx.x * blockDim.x + threadIdx.x;
    if (e < M) atomicAdd(&g_deg[__ldg(&ei[M + e])], 1);
}

// Triplet message receive; stage t' in d_out; premultiplied tri; edge base.
__global__ void k_node1(const float* __restrict__ ec,
                        const float* __restrict__ t12, const float* __restrict__ t13,
                        const float* __restrict__ t23,
                        const int* __restrict__ c12, const int* __restrict__ c13,
                        const int* __restrict__ c23,
                        const float* __restrict__ cnt,
                        float* __restrict__ o_ec,
                        float* __restrict__ o_t12, float* __restrict__ o_t13,
                        float* __restrict__ o_t23, int T, int E) {
    int i = blockIdx.x * blockDim.x + threadIdx.x;
    if (i >= T) return;
    if (i < E) o_ec[i] = (cnt[i] > 0.f) ? 0.f : ec[i];   // fused edge-base pass
    int i12 = c12[i], i13 = c13[i], i23 = c23[i];
    float a = t12[i] + ec[i12] / cnt[i12];
    float b = t13[i] + ec[i13] / cnt[i13];
    float c = t23[i] + ec[i23] / cnt[i23];
    o_t12[i] = a; o_t13[i] = b; o_t23[i] = c;
    float dis = rsqrtf((float)g_deg[i] + 1.0f);
    g_tri4[i] = make_float4(a * dis, b * dis, c * dis, 0.f);
}

// ---- exclusive scan of g_deg -> g_off (3 kernels) ----
__global__ void k_scanA(int T) {
    __shared__ int sh[256];
    int b = blockIdx.x, tx = threadIdx.x;
    int base = b * SCAN_E + tx * 8;
    int s = 0;
#pragma unroll
    for (int k = 0; k < 8; k++) { int i = base + k; if (i < T) s += g_deg[i]; }
    sh[tx] = s; __syncthreads();
    for (int o = 128; o > 0; o >>= 1) { if (tx < o) sh[tx] += sh[tx + o]; __syncthreads(); }
    if (tx == 0) g_bsum[b] = sh[0];
}

__global__ void k_scanB(int nb, int T) {
    __shared__ int sh[1024];
    int tx = threadIdx.x;
    int c = (nb + 1023) >> 10;
    int s = 0;
    for (int k = 0; k < c; k++) { int i = tx * c + k; if (i < nb) s += g_bsum[i]; }
    sh[tx] = s; __syncthreads();
    for (int o = 1; o < 1024; o <<= 1) {
        int v = (tx >= o) ? sh[tx - o] : 0; __syncthreads();
        sh[tx] += v; __syncthreads();
    }
    if (tx == 1023) g_off[T] = sh[1023];       // sentinel: total edge count
    int excl = (tx == 0) ? 0 : sh[tx - 1];
    for (int k = 0; k < c; k++) {
        int i = tx * c + k;
        if (i < nb) { int v = g_bsum[i]; g_bsum[i] = excl; excl += v; }
    }
}

__global__ void k_scanC(int T) {
    __shared__ int sh[256];
    int b = blockIdx.x, tx = threadIdx.x;
    int base = b * SCAN_E + tx * 8;
    int loc[8]; int s = 0;
#pragma unroll
    for (int k = 0; k < 8; k++) {
        int i = base + k;
        int d = (i < T) ? g_deg[i] : 0;
        loc[k] = s; s += d;
    }
    sh[tx] = s; __syncthreads();
    for (int o = 1; o < 256; o <<= 1) {
        int v = (tx >= o) ? sh[tx - o] : 0; __syncthreads();
        sh[tx] += v; __syncthreads();
    }
    int toff = ((tx == 0) ? 0 : sh[tx - 1]) + g_bsum[b];
#pragma unroll
    for (int k = 0; k < 8; k++) {
        int i = base + k;
        if (i < T) { int o = toff + loc[k]; g_off[i] = o; g_cursor[i] = o; }
    }
}

// Fill CSR: src lists grouped by dst.
__global__ void k_csr(const int* __restrict__ ei, int M) {
    int e = blockIdx.x * blockDim.x + threadIdx.x;
    if (e >= M) return;
    int src = __ldg(&ei[e]);
    int dst = __ldg(&ei[M + e]);
    int pos = atomicAdd(&g_cursor[dst], 1);
    g_csr[pos] = src;
}

// Layer 1 (fused): gather+sum raw 3-dim messages (MLP-batched), @W1+b1, relu,
// store h*dis as fp16.
__global__ void k_layer1(const float* __restrict__ W1, const float* __restrict__ b1, int T) {
    __shared__ float W1s[96];
    __shared__ float b1s[HID];
    int tx = threadIdx.x;
    if (tx < 96)  W1s[tx] = W1[tx];
    if (tx < HID) b1s[tx] = b1[tx];
    __syncthreads();
    int i = blockIdx.x * blockDim.x + tx;
    if (i >= T) return;

    int s = g_off[i];
    int d = g_off[i + 1] - s;
    float dis = rsqrtf((float)d + 1.0f);

    float4 sum = g_tri4[i];                 // self loop (already *dis_i)
    int n = 0;
    for (; n + 4 <= d; n += 4) {            // 4-way MLP batch
        int s0 = g_csr[s+n], s1 = g_csr[s+n+1], s2 = g_csr[s+n+2], s3 = g_csr[s+n+3];
        float4 t0 = g_tri4[s0];
        float4 t1 = g_tri4[s1];
        float4 t2 = g_tri4[s2];
        float4 t3 = g_tri4[s3];
        sum.x += t0.x + t1.x + t2.x + t3.x;
        sum.y += t0.y + t1.y + t2.y + t3.y;
        sum.z += t0.z + t1.z + t2.z + t3.z;
    }
    for (; n < d; n++) {
        float4 t = g_tri4[g_csr[s + n]];
        sum.x += t.x; sum.y += t.y; sum.z += t.z;
    }
    float va = dis * sum.x, vb = dis * sum.y, vc = dis * sum.z;

    float h[HID];
#pragma unroll
    for (int j = 0; j < HID; j++)
        h[j] = fmaxf(va * W1s[j] + vb * W1s[32 + j] + vc * W1s[64 + j] + b1s[j], 0.f) * dis;

    uint4* ph = g_hs4 + (size_t)i * 4;
#pragma unroll
    for (int q = 0; q < 4; q++) {           // each uint4 packs 8 halves
        uint4 u;
        u.x = h2_to_u32(__floats2half2_rn(h[8*q+0], h[8*q+1]));
        u.y = h2_to_u32(__floats2half2_rn(h[8*q+2], h[8*q+3]));
        u.z = h2_to_u32(__floats2half2_rn(h[8*q+4], h[8*q+5]));
        u.w = h2_to_u32(__floats2half2_rn(h[8*q+6], h[8*q+7]));
        ph[q] = u;
    }
}

__device__ __forceinline__ void acc_u4(float* sum, uint4 u) {
    float2 f0 = __half22float2(u32_to_h2(u.x));
    float2 f1 = __half22float2(u32_to_h2(u.y));
    float2 f2 = __half22float2(u32_to_h2(u.z));
    float2 f3 = __half22float2(u32_to_h2(u.w));
    sum[0]+=f0.x; sum[1]+=f0.y; sum[2]+=f1.x; sum[3]+=f1.y;
    sum[4]+=f2.x; sum[5]+=f2.y; sum[6]+=f3.x; sum[7]+=f3.y;
}

// Layer 2 + head (fused), 4 lanes per dst node; fp16 message gather (MLP-batched),
// fp32 accum, W2 matmul via shfl, head matmul + reductions, t/edge updates.
__global__ void k_layer2_final(const float* __restrict__ W2, const float* __restrict__ b2,
                               const float* __restrict__ Wout, const float* __restrict__ bout,
                               const int* __restrict__ c12, const int* __restrict__ c13,
                               const int* __restrict__ c23,
                               float* __restrict__ o_ec,
                               float* __restrict__ o_t12, float* __restrict__ o_t13,
                               float* __restrict__ o_t23, int T) {
    __shared__ float4 W2s[HID * 8];   // W2[k][j] as float4 over j
    __shared__ float  b2s[HID];
    __shared__ float  Wos[96];
    __shared__ float  bos[3];
    int tx = threadIdx.x;
    W2s[tx] = ((const float4*)W2)[tx];
    if (tx < HID) b2s[tx] = b2[tx];
    if (tx < 96)  Wos[tx] = Wout[tx];
    if (tx < 3)   bos[tx] = bout[tx];
    __syncthreads();

    int tid = blockIdx.x * blockDim.x + tx;
    int i  = tid >> 2;
    if (i >= T) return;
    int l4 = tx & 3;                  // lane owns h components [8*l4, 8*l4+8)

    int s = g_off[i];
    int d = g_off[i + 1] - s;
    float dis = rsqrtf((float)d + 1.0f);

    float sum[8];
    {
        uint4 u = g_hs4[(size_t)i * 4 + l4];      // self loop (already *dis_i)
        float2 f0 = __half22float2(u32_to_h2(u.x));
        float2 f1 = __half22float2(u32_to_h2(u.y));
        float2 f2 = __half22float2(u32_to_h2(u.z));
        float2 f3 = __half22float2(u32_to_h2(u.w));
        sum[0]=f0.x; sum[1]=f0.y; sum[2]=f1.x; sum[3]=f1.y;
        sum[4]=f2.x; sum[5]=f2.y; sum[6]=f3.x; sum[7]=f3.y;
    }
    int n = 0;
    for (; n + 4 <= d; n += 4) {              // 4-way MLP batch
        int s0 = g_csr[s+n], s1 = g_csr[s+n+1], s2 = g_csr[s+n+2], s3 = g_csr[s+n+3];
        uint4 u0 = g_hs4[(size_t)s0 * 4 + l4];
        uint4 u1 = g_hs4[(size_t)s1 * 4 + l4];
        uint4 u2 = g_hs4[(size_t)s2 * 4 + l4];
        uint4 u3 = g_hs4[(size_t)s3 * 4 + l4];
        acc_u4(sum, u0); acc_u4(sum, u1); acc_u4(sum, u2); acc_u4(sum, u3);
    }
    for (; n < d; n++) {
        uint4 u = g_hs4[(size_t)g_csr[s + n] * 4 + l4];
        acc_u4(sum, u);
    }
    float vr[8];
#pragma unroll
    for (int r = 0; r < 8; r++) vr[r] = dis * sum[r];

    float acc[8];
#pragma unroll
    for (int r = 0; r < 8; r++) acc[r] = b2s[8 * l4 + r];
#pragma unroll
    for (int k = 0; k < HID; k++) {
        float vk = __shfl_sync(0xffffffffu, vr[k & 7], k >> 3, 4);
        float4 wa = W2s[k * 8 + 2 * l4];
        float4 wb = W2s[k * 8 + 2 * l4 + 1];
        acc[0] += vk * wa.x; acc[1] += vk * wa.y; acc[2] += vk * wa.z; acc[3] += vk * wa.w;
        acc[4] += vk * wb.x; acc[5] += vk * wb.y; acc[6] += vk * wb.z; acc[7] += vk * wb.w;
    }

    float d0 = 0.f, d1 = 0.f, d2 = 0.f;
#pragma unroll
    for (int r = 0; r < 8; r++) {
        float hj = fmaxf(acc[r], 0.f);
        int j = 8 * l4 + r;
        d0 += hj * Wos[j * 3 + 0];
        d1 += hj * Wos[j * 3 + 1];
        d2 += hj * Wos[j * 3 + 2];
    }
#pragma unroll
    for (int o = 1; o < 4; o <<= 1) {
        d0 += __shfl_xor_sync(0xffffffffu, d0, o, 4);
        d1 += __shfl_xor_sync(0xffffffffu, d1, o, 4);
        d2 += __shfl_xor_sync(0xffffffffu, d2, o, 4);
    }
    if (l4 == 0) {
        d0 += bos[0]; d1 += bos[1]; d2 += bos[2];
        o_t12[i] = o_t12[i] - d0;
        o_t13[i] = o_t13[i] - d1;
        o_t23[i] = o_t23[i] - d2;
        atomicAdd(&o_ec[c12[i]], d0);
        atomicAdd(&o_ec[c13[i]], d1);
        atomicAdd(&o_ec[c23[i]], d2);
    }
}

extern "C" void kernel_launch(void* const* d_in, const int* in_sizes, int n_in,
                              void* d_out, int out_size) {
    const float* ec   = (const float*)d_in[0];
    const float* t12  = (const float*)d_in[1];
    const float* t13  = (const float*)d_in[2];
    const float* t23  = (const float*)d_in[3];
    const int*   c12  = (const int*)  d_in[4];
    const int*   c13  = (const int*)  d_in[5];
    const int*   c23  = (const int*)  d_in[6];
    const float* cnt  = (const float*)d_in[7];
    const int*   ei   = (const int*)  d_in[8];
    const float* W1   = (const float*)d_in[9];
    const float* b1   = (const float*)d_in[10];
    const float* W2   = (const float*)d_in[11];
    const float* b2   = (const float*)d_in[12];
    const float* Wout = (const float*)d_in[13];
    const float* bout = (const float*)d_in[14];

    int E = in_sizes[0];
    int T = in_sizes[1];
    int M = in_sizes[8] / 2;

    float* o     = (float*)d_out;
    float* o_ec  = o;
    float* o_t12 = o + E;
    float* o_t13 = o + E + (size_t)T;
    float* o_t23 = o + E + (size_t)2 * T;

    const int B = 256;
    int gT  = (T + B - 1) / B;
    int gM  = (M + B - 1) / B;
    int nb  = (T + SCAN_E - 1) / SCAN_E;       // scan blocks
    int gL2 = (int)(((size_t)T * 4 + B - 1) / B);

    k_zero_deg<<<gT, B>>>(T);
    k_degree<<<gM, B>>>(ei, M);
    k_node1<<<gT, B>>>(ec, t12, t13, t23, c12, c13, c23, cnt,
                       o_ec, o_t12, o_t13, o_t23, T, E);
    k_scanA<<<nb, B>>>(T);
    k_scanB<<<1, 1024>>>(nb, T);
    k_scanC<<<nb, B>>>(T);
    k_csr<<<gM, B>>>(ei, M);
    k_layer1<<<gT, B>>>(W1, b1, T);
    k_layer2_final<<<gL2, B>>>(W2, b2, Wout, bout, c12, c13, c23,
                               o_ec, o_t12, o_t13, o_t23, T);
}